// round 13
// baseline (speedup 1.0000x reference)
#include <cuda_runtime.h>
#include <cstdint>
#include <math.h>

#define HIDDEN  2048
#define S_LEN   2048
#define NH      32
#define NKV     8
#define HD      64
#define KV_W    (NKV * HD)   // 512

// ---------------- scratch (static device arrays; no allocation) ----------------
__device__ float g_Q[S_LEN * HIDDEN];   // [s, h*64+d]  (rotated in place)
__device__ float g_K[S_LEN * KV_W];     // [s, kvh*64+d] (rotated in place)
__device__ float g_V[S_LEN * KV_W];
__device__ float g_O[S_LEN * HIDDEN];   // attention output, [s, h*64+d]

// ---------------- tiled fp32 SGEMM: C[M,N] = A[M,K] @ B[K,N] ----------------
__global__ __launch_bounds__(256)
void sgemm128(const float* __restrict__ A, const float* __restrict__ B,
              float* __restrict__ C, int M, int N, int K)
{
    const int BM = 128, BN = 128, BK = 8, TM = 8, TN = 8;
    __shared__ float As[BK][BM];
    __shared__ float Bs[BK][BN];

    const int tid = threadIdx.x;
    const int threadCol = tid % (BN / TN);
    const int threadRow = tid / (BN / TN);

    A += (size_t)blockIdx.y * BM * K;
    B += (size_t)blockIdx.x * BN;
    C += (size_t)blockIdx.y * BM * N + (size_t)blockIdx.x * BN;

    const int innerRowA = tid / (BK / 4);
    const int innerColA = tid % (BK / 4);
    const int innerRowB = tid / (BN / 4);
    const int innerColB = tid % (BN / 4);

    float acc[TM][TN];
    #pragma unroll
    for (int i = 0; i < TM; i++)
        #pragma unroll
        for (int j = 0; j < TN; j++) acc[i][j] = 0.0f;

    float regM[TM], regN[TN];

    for (int k0 = 0; k0 < K; k0 += BK) {
        float4 a4 = *reinterpret_cast<const float4*>(
            A + (size_t)innerRowA * K + k0 + innerColA * 4);
        As[innerColA * 4 + 0][innerRowA] = a4.x;
        As[innerColA * 4 + 1][innerRowA] = a4.y;
        As[innerColA * 4 + 2][innerRowA] = a4.z;
        As[innerColA * 4 + 3][innerRowA] = a4.w;

        float4 b4 = *reinterpret_cast<const float4*>(
            B + (size_t)(k0 + innerRowB) * N + innerColB * 4);
        *reinterpret_cast<float4*>(&Bs[innerRowB][innerColB * 4]) = b4;

        __syncthreads();

        #pragma unroll
        for (int k = 0; k < BK; k++) {
            #pragma unroll
            for (int i = 0; i < TM; i++) regM[i] = As[k][threadRow * TM + i];
            #pragma unroll
            for (int j = 0; j < TN; j++) regN[j] = Bs[k][threadCol * TN + j];
            #pragma unroll
            for (int i = 0; i < TM; i++)
                #pragma unroll
                for (int j = 0; j < TN; j++)
                    acc[i][j] = fmaf(regM[i], regN[j], acc[i][j]);
        }
        __syncthreads();
    }

    #pragma unroll
    for (int i = 0; i < TM; i++) {
        #pragma unroll
        for (int j4 = 0; j4 < TN / 4; j4++) {
            float4 v;
            v.x = acc[i][j4 * 4 + 0];
            v.y = acc[i][j4 * 4 + 1];
            v.z = acc[i][j4 * 4 + 2];
            v.w = acc[i][j4 * 4 + 3];
            *reinterpret_cast<float4*>(
                C + (size_t)(threadRow * TM + i) * N + threadCol * TN + j4 * 4) = v;
        }
    }
}

// ---------------- RoPE (half-split, theta=10000), ANGLE NEGATED, Q and K -------
// One thread per (s, head, freq-pair i<32). h < NH -> Q, else K. In place.
// Executed-reference rotation: x0' = x0*c + x1*s ; x1' = x1*c - x0*s
__global__ void rope_neg(float* __restrict__ Q, float* __restrict__ K,
                         const int* __restrict__ pos_ids)
{
    const int total = S_LEN * (NH + NKV) * 32;
    int idx = blockIdx.x * blockDim.x + threadIdx.x;
    if (idx >= total) return;

    int i = idx & 31;                  // freq index 0..31
    int h = (idx >> 5) % (NH + NKV);   // 0..39
    int s = idx / ((NH + NKV) * 32);

    float p = (float)pos_ids[s];       // int32 arange
    // inv_freq = 1 / 10000^(2i/64)
    float inv_freq = exp2f(-((float)i * (1.0f / 32.0f)) * 13.287712379549449f);
    float ang = p * inv_freq;
    float c, sn;
    sincosf(ang, &c, &sn);

    float* base = (h < NH) ? (Q + (size_t)s * HIDDEN + h * HD)
                           : (K + (size_t)s * KV_W + (h - NH) * HD);
    float x0 = base[i];
    float x1 = base[i + 32];
    base[i]      = x0 * c + x1 * sn;   // NEGATED angle vs displayed reference
    base[i + 32] = x1 * c - x0 * sn;
}

// ---------------- causal flash attention (GQA) ----------------
// grid: (S/64 query tiles, 32 heads), block: 64 threads (1 query row/thread).
__global__ __launch_bounds__(64)
void flash_attn(const float* __restrict__ Q, const float* __restrict__ K,
                const float* __restrict__ V, float* __restrict__ O)
{
    __shared__ float Ks[64][64];
    __shared__ float Vs[64][64];

    const int t    = threadIdx.x;
    const int head = blockIdx.y;
    const int kvh  = head >> 2;      // N_REP = 4
    const int qt   = blockIdx.x;
    const int q    = qt * 64 + t;

    float qreg[64];
    const float* qptr = Q + (size_t)q * HIDDEN + head * HD;
    #pragma unroll
    for (int d = 0; d < 64; d++) qreg[d] = qptr[d] * 0.125f;  // 1/sqrt(64)

    float o[64];
    #pragma unroll
    for (int d = 0; d < 64; d++) o[d] = 0.0f;
    float m = -1e30f, l = 0.0f;

    for (int jt = 0; jt <= qt; ++jt) {
        const float* kbase = K + (size_t)(jt * 64) * KV_W + kvh * HD;
        const float* vbase = V + (size_t)(jt * 64) * KV_W + kvh * HD;
        __syncthreads();
        #pragma unroll 8
        for (int i = 0; i < 64; i++) {
            Ks[i][t] = kbase[(size_t)i * KV_W + t];
            Vs[i][t] = vbase[(size_t)i * KV_W + t];
        }
        __syncthreads();

        const bool diag = (jt == qt);

        for (int jc = 0; jc < 64; jc += 16) {
            float sv[16];
            #pragma unroll
            for (int jj = 0; jj < 16; jj++) {
                const float4* kr = reinterpret_cast<const float4*>(Ks[jc + jj]);
                float a0 = 0.f, a1 = 0.f, a2 = 0.f, a3 = 0.f;
                #pragma unroll
                for (int d4 = 0; d4 < 16; d4++) {
                    float4 kv = kr[d4];
                    a0 = fmaf(qreg[d4 * 4 + 0], kv.x, a0);
                    a1 = fmaf(qreg[d4 * 4 + 1], kv.y, a1);
                    a2 = fmaf(qreg[d4 * 4 + 2], kv.z, a2);
                    a3 = fmaf(qreg[d4 * 4 + 3], kv.w, a3);
                }
                float sc = (a0 + a1) + (a2 + a3);
                if (diag && (jc + jj) > t) sc = -1e30f;   // causal mask
                sv[jj] = sc;
            }

            float mn = m;
            #pragma unroll
            for (int jj = 0; jj < 16; jj++) mn = fmaxf(mn, sv[jj]);
            float alpha = __expf(m - mn);
            l *= alpha;
            #pragma unroll
            for (int d = 0; d < 64; d++) o[d] *= alpha;

            #pragma unroll
            for (int jj = 0; jj < 16; jj++) {
                float p = __expf(sv[jj] - mn);
                l += p;
                const float4* vr = reinterpret_cast<const float4*>(Vs[jc + jj]);
                #pragma unroll
                for (int d4 = 0; d4 < 16; d4++) {
                    float4 vv = vr[d4];
                    o[d4 * 4 + 0] = fmaf(p, vv.x, o[d4 * 4 + 0]);
                    o[d4 * 4 + 1] = fmaf(p, vv.y, o[d4 * 4 + 1]);
                    o[d4 * 4 + 2] = fmaf(p, vv.z, o[d4 * 4 + 2]);
                    o[d4 * 4 + 3] = fmaf(p, vv.w, o[d4 * 4 + 3]);
                }
            }
            m = mn;
        }
    }

    float inv_l = 1.0f / l;
    float* optr = O + (size_t)q * HIDDEN + head * HD;
    #pragma unroll
    for (int d = 0; d < 64; d++) optr[d] = o[d] * inv_l;
}

// ---------------- launch ----------------
extern "C" void kernel_launch(void* const* d_in, const int* in_sizes, int n_in,
                              void* d_out, int out_size)
{
    // size-based input identification
    int big[3], bn = 0;
    int med[2], md = 0;
    int posIdx = 5;
    for (int i = 0; i < n_in; i++) {
        if (in_sizes[i] == HIDDEN * HIDDEN)    { if (bn < 3) big[bn++] = i; }
        else if (in_sizes[i] == HIDDEN * KV_W) { if (md < 2) med[md++] = i; }
        else                                   { posIdx = i; }
    }
    int iX, iWq, iWo;
    if (bn == 3 && big[0] == 0) { iX = big[0]; iWq = big[1]; iWo = big[2]; }
    else if (bn == 3)           { iWo = big[0]; iWq = big[1]; iX = big[2]; }
    else                        { iX = 0; iWq = 1; iWo = 4; }
    int iWk = (md == 2) ? med[0] : 2;
    int iWv = (md == 2) ? med[1] : 3;

    const float* X   = (const float*)d_in[iX];
    const float* Wq  = (const float*)d_in[iWq];
    const float* Wk  = (const float*)d_in[iWk];
    const float* Wv  = (const float*)d_in[iWv];
    const float* Wo  = (const float*)d_in[iWo];
    const int*   pos = (const int*)d_in[posIdx];
    float* out = (float*)d_out;

    float *Qp, *Kp, *Vp, *Op;
    cudaGetSymbolAddress((void**)&Qp, g_Q);
    cudaGetSymbolAddress((void**)&Kp, g_K);
    cudaGetSymbolAddress((void**)&Vp, g_V);
    cudaGetSymbolAddress((void**)&Op, g_O);

    // QKV projections
    sgemm128<<<dim3(HIDDEN / 128, S_LEN / 128), 256>>>(X, Wq, Qp, S_LEN, HIDDEN, HIDDEN);
    sgemm128<<<dim3(KV_W   / 128, S_LEN / 128), 256>>>(X, Wk, Kp, S_LEN, KV_W,  HIDDEN);
    sgemm128<<<dim3(KV_W   / 128, S_LEN / 128), 256>>>(X, Wv, Vp, S_LEN, KV_W,  HIDDEN);

    // RoPE on Q and K, angle negated
    {
        int total = S_LEN * (NH + NKV) * 32;
        rope_neg<<<(total + 255) / 256, 256>>>(Qp, Kp, pos);
    }

    // causal flash attention
    flash_attn<<<dim3(S_LEN / 64, NH), 64>>>(Qp, Kp, Vp, Op);

    // output projection
    sgemm128<<<dim3(HIDDEN / 128, S_LEN / 128), 256>>>(Op, Wo, out, S_LEN, HIDDEN, HIDDEN);
}

// round 14
// speedup vs baseline: 1.3320x; 1.3320x over previous
#include <cuda_runtime.h>
#include <cstdint>
#include <math.h>

#define HIDDEN  2048
#define S_LEN   2048
#define NH      32
#define NKV     8
#define HD      64
#define KV_W    (NKV * HD)   // 512

// ---------------- scratch (static device arrays; no allocation) ----------------
__device__ float g_Q[S_LEN * HIDDEN];   // [s, h*64+d]  (rotated in place)
__device__ float g_K[S_LEN * KV_W];     // [s, kvh*64+d] (rotated in place)
__device__ float g_V[S_LEN * KV_W];
__device__ float g_O[S_LEN * HIDDEN];   // attention output, [s, h*64+d]

// ---------------- tiled fp32 SGEMM (128x128x8), register-prefetch ----------------
__global__ __launch_bounds__(256)
void sgemm128(const float* __restrict__ A, const float* __restrict__ B,
              float* __restrict__ C, int M, int N, int K)
{
    const int BK = 8, TM = 8, TN = 8;
    __shared__ float As[BK][128];
    __shared__ float Bs[BK][128];

    const int tid = threadIdx.x;
    const int threadCol = tid % 16;
    const int threadRow = tid / 16;

    A += (size_t)blockIdx.y * 128 * K;
    B += (size_t)blockIdx.x * 128;
    C += (size_t)blockIdx.y * 128 * N + (size_t)blockIdx.x * 128;

    const int irA = tid / 2, icA = tid % 2;
    const int irB = tid / 32, icB = tid % 32;

    float4 a4 = *reinterpret_cast<const float4*>(A + (size_t)irA * K + icA * 4);
    float4 b4 = *reinterpret_cast<const float4*>(B + (size_t)irB * N + icB * 4);

    float acc[TM][TN];
    #pragma unroll
    for (int i = 0; i < TM; i++)
        #pragma unroll
        for (int j = 0; j < TN; j++) acc[i][j] = 0.0f;

    float regM[TM], regN[TN];

    for (int k0 = 0; k0 < K; k0 += BK) {
        As[icA * 4 + 0][irA] = a4.x;
        As[icA * 4 + 1][irA] = a4.y;
        As[icA * 4 + 2][irA] = a4.z;
        As[icA * 4 + 3][irA] = a4.w;
        *reinterpret_cast<float4*>(&Bs[irB][icB * 4]) = b4;
        __syncthreads();

        if (k0 + BK < K) {   // prefetch next tile while computing
            a4 = *reinterpret_cast<const float4*>(A + (size_t)irA * K + (k0 + BK) + icA * 4);
            b4 = *reinterpret_cast<const float4*>(B + (size_t)(k0 + BK + irB) * N + icB * 4);
        }

        #pragma unroll
        for (int k = 0; k < BK; k++) {
            #pragma unroll
            for (int i = 0; i < TM; i++) regM[i] = As[k][threadRow * TM + i];
            #pragma unroll
            for (int j = 0; j < TN; j++) regN[j] = Bs[k][threadCol * TN + j];
            #pragma unroll
            for (int i = 0; i < TM; i++)
                #pragma unroll
                for (int j = 0; j < TN; j++)
                    acc[i][j] = fmaf(regM[i], regN[j], acc[i][j]);
        }
        __syncthreads();
    }

    #pragma unroll
    for (int i = 0; i < TM; i++) {
        #pragma unroll
        for (int j4 = 0; j4 < TN / 4; j4++) {
            float4 v;
            v.x = acc[i][j4 * 4 + 0];
            v.y = acc[i][j4 * 4 + 1];
            v.z = acc[i][j4 * 4 + 2];
            v.w = acc[i][j4 * 4 + 3];
            *reinterpret_cast<float4*>(
                C + (size_t)(threadRow * TM + i) * N + threadCol * TN + j4 * 4) = v;
        }
    }
}

// ---------------- SGEMM 128x64x8 (for N=512: grid (8,16)=128 blocks) ----------------
__global__ __launch_bounds__(256)
void sgemm128x64(const float* __restrict__ A, const float* __restrict__ B,
                 float* __restrict__ C, int M, int N, int K)
{
    const int BK = 8, TM = 8, TN = 4;
    __shared__ float As[BK][128];
    __shared__ float Bs[BK][64];

    const int tid = threadIdx.x;
    const int threadCol = tid % 16;   // *4 -> 64 cols
    const int threadRow = tid / 16;   // *8 -> 128 rows

    A += (size_t)blockIdx.y * 128 * K;
    B += (size_t)blockIdx.x * 64;
    C += (size_t)blockIdx.y * 128 * N + (size_t)blockIdx.x * 64;

    const int irA = tid / 2, icA = tid % 2;
    const int irB = tid / 16, icB = tid % 16;   // only tid<128 loads B

    float4 a4 = *reinterpret_cast<const float4*>(A + (size_t)irA * K + icA * 4);
    float4 b4 = make_float4(0.f, 0.f, 0.f, 0.f);
    if (tid < 128)
        b4 = *reinterpret_cast<const float4*>(B + (size_t)irB * N + icB * 4);

    float acc[TM][TN];
    #pragma unroll
    for (int i = 0; i < TM; i++)
        #pragma unroll
        for (int j = 0; j < TN; j++) acc[i][j] = 0.0f;

    float regM[TM], regN[TN];

    for (int k0 = 0; k0 < K; k0 += BK) {
        As[icA * 4 + 0][irA] = a4.x;
        As[icA * 4 + 1][irA] = a4.y;
        As[icA * 4 + 2][irA] = a4.z;
        As[icA * 4 + 3][irA] = a4.w;
        if (tid < 128)
            *reinterpret_cast<float4*>(&Bs[irB][icB * 4]) = b4;
        __syncthreads();

        if (k0 + BK < K) {
            a4 = *reinterpret_cast<const float4*>(A + (size_t)irA * K + (k0 + BK) + icA * 4);
            if (tid < 128)
                b4 = *reinterpret_cast<const float4*>(B + (size_t)(k0 + BK + irB) * N + icB * 4);
        }

        #pragma unroll
        for (int k = 0; k < BK; k++) {
            #pragma unroll
            for (int i = 0; i < TM; i++) regM[i] = As[k][threadRow * TM + i];
            #pragma unroll
            for (int j = 0; j < TN; j++) regN[j] = Bs[k][threadCol * TN + j];
            #pragma unroll
            for (int i = 0; i < TM; i++)
                #pragma unroll
                for (int j = 0; j < TN; j++)
                    acc[i][j] = fmaf(regM[i], regN[j], acc[i][j]);
        }
        __syncthreads();
    }

    #pragma unroll
    for (int i = 0; i < TM; i++) {
        float4 v;
        v.x = acc[i][0]; v.y = acc[i][1]; v.z = acc[i][2]; v.w = acc[i][3];
        *reinterpret_cast<float4*>(
            C + (size_t)(threadRow * TM + i) * N + threadCol * 4) = v;
    }
}

// ---------------- RoPE (half-split, theta=10000), ANGLE NEGATED — DO NOT CHANGE ----
__global__ void rope_neg(float* __restrict__ Q, float* __restrict__ K,
                         const int* __restrict__ pos_ids)
{
    const int total = S_LEN * (NH + NKV) * 32;
    int idx = blockIdx.x * blockDim.x + threadIdx.x;
    if (idx >= total) return;

    int i = idx & 31;
    int h = (idx >> 5) % (NH + NKV);
    int s = idx / ((NH + NKV) * 32);

    float p = (float)pos_ids[s];
    float inv_freq = exp2f(-((float)i * (1.0f / 32.0f)) * 13.287712379549449f);
    float ang = p * inv_freq;
    float c, sn;
    sincosf(ang, &c, &sn);

    float* base = (h < NH) ? (Q + (size_t)s * HIDDEN + h * HD)
                           : (K + (size_t)s * KV_W + (h - NH) * HD);
    float x0 = base[i];
    float x1 = base[i + 32];
    base[i]      = x0 * c + x1 * sn;   // negated angle (executed-reference behavior)
    base[i + 32] = x1 * c - x0 * sn;
}

// ---------------- register-tiled causal flash attention ----------------
// grid (S/64, NH), block 256 = 16x16 threads, 4x4 micro-tile each.
// smem: Qs[d][q] 16KB, KsPs (Ks[d][j] then reused as Ps[j][q]) 16KB, Vs[j][d] 16KB = 48KB.
// Ks/Ps use xor-group swizzle on the column-group index to kill bank conflicts.
__global__ __launch_bounds__(256)
void flash_tile(const float* __restrict__ Q, const float* __restrict__ K,
                const float* __restrict__ V, float* __restrict__ O)
{
    __shared__ float Qs[64 * 64];     // [d][q] plain (one-time load)
    __shared__ float KsPs[64 * 64];   // swizzled: [row][ ((col>>2)^(row&7))*4 + (col&3) ]
    __shared__ float Vs[64 * 64];     // [j][d] natural

    const int tid = threadIdx.x;
    const int tx = tid & 15;          // key-group / dim-group
    const int ty = tid >> 4;          // query-group
    const int head = blockIdx.y;
    const int kvh  = head >> 2;
    const int qt   = blockIdx.x;
    const int q0   = qt * 64;

    // load Q tile transposed + prescaled
    for (int i = tid; i < 4096; i += 256) {
        int d = i & 63, qq = i >> 6;
        Qs[d * 64 + qq] = Q[(size_t)(q0 + qq) * HIDDEN + head * HD + d] * 0.125f;
    }

    float m[4], l[4], o[4][4];
    #pragma unroll
    for (int i = 0; i < 4; i++) {
        m[i] = -1e30f; l[i] = 0.0f;
        #pragma unroll
        for (int j = 0; j < 4; j++) o[i][j] = 0.0f;
    }

    for (int jt = 0; jt <= qt; jt++) {
        __syncthreads();   // previous AV reads done
        // load K transposed+swizzled [d][j], V natural [j][d]
        for (int i = tid; i < 4096; i += 256) {
            int d = i & 63, jj = i >> 6;
            float kval = K[(size_t)(jt * 64 + jj) * KV_W + kvh * HD + d];
            KsPs[d * 64 + ((((jj >> 2) ^ (d & 7)) << 2) | (jj & 3))] = kval;
            Vs[jj * 64 + d] = V[(size_t)(jt * 64 + jj) * KV_W + kvh * HD + d];
        }
        __syncthreads();

        // S[4q][4j] = Q^T K
        float s[4][4];
        #pragma unroll
        for (int i = 0; i < 4; i++)
            #pragma unroll
            for (int j = 0; j < 4; j++) s[i][j] = 0.0f;

        #pragma unroll
        for (int k = 0; k < 64; k++) {
            float4 qv = *reinterpret_cast<const float4*>(&Qs[k * 64 + ty * 4]);
            float4 kv = *reinterpret_cast<const float4*>(
                &KsPs[k * 64 + ((tx ^ (k & 7)) << 2)]);
            s[0][0] = fmaf(qv.x, kv.x, s[0][0]); s[0][1] = fmaf(qv.x, kv.y, s[0][1]);
            s[0][2] = fmaf(qv.x, kv.z, s[0][2]); s[0][3] = fmaf(qv.x, kv.w, s[0][3]);
            s[1][0] = fmaf(qv.y, kv.x, s[1][0]); s[1][1] = fmaf(qv.y, kv.y, s[1][1]);
            s[1][2] = fmaf(qv.y, kv.z, s[1][2]); s[1][3] = fmaf(qv.y, kv.w, s[1][3]);
            s[2][0] = fmaf(qv.z, kv.x, s[2][0]); s[2][1] = fmaf(qv.z, kv.y, s[2][1]);
            s[2][2] = fmaf(qv.z, kv.z, s[2][2]); s[2][3] = fmaf(qv.z, kv.w, s[2][3]);
            s[3][0] = fmaf(qv.w, kv.x, s[3][0]); s[3][1] = fmaf(qv.w, kv.y, s[3][1]);
            s[3][2] = fmaf(qv.w, kv.z, s[3][2]); s[3][3] = fmaf(qv.w, kv.w, s[3][3]);
        }

        if (jt == qt) {   // causal mask on diagonal tile
            #pragma unroll
            for (int i = 0; i < 4; i++)
                #pragma unroll
                for (int j = 0; j < 4; j++)
                    if (tx * 4 + j > ty * 4 + i) s[i][j] = -1e30f;
        }

        __syncthreads();   // all Ks reads done before Ps overwrites the buffer

        // online softmax + write P (swizzled [j][q]) + rescale o
        #pragma unroll
        for (int i = 0; i < 4; i++) {
            float mx = fmaxf(fmaxf(s[i][0], s[i][1]), fmaxf(s[i][2], s[i][3]));
            #pragma unroll
            for (int ofs = 8; ofs > 0; ofs >>= 1)
                mx = fmaxf(mx, __shfl_xor_sync(0xffffffffu, mx, ofs));
            float mn = fmaxf(m[i], mx);
            float alpha = __expf(m[i] - mn);
            m[i] = mn;
            float sum = 0.0f;
            #pragma unroll
            for (int j = 0; j < 4; j++) {
                float pv = __expf(s[i][j] - mn);
                int jrow = tx * 4 + j;
                KsPs[jrow * 64 + (((ty ^ (jrow & 7)) << 2) | i)] = pv;
                sum += pv;
            }
            #pragma unroll
            for (int ofs = 8; ofs > 0; ofs >>= 1)
                sum += __shfl_xor_sync(0xffffffffu, sum, ofs);
            l[i] = l[i] * alpha + sum;
            #pragma unroll
            for (int j = 0; j < 4; j++) o[i][j] *= alpha;
        }
        __syncthreads();   // Ps visible to all

        // O[4q][4d] += P[4q][j] * V[j][4d]
        #pragma unroll
        for (int k = 0; k < 64; k++) {
            float4 pv = *reinterpret_cast<const float4*>(
                &KsPs[k * 64 + ((ty ^ (k & 7)) << 2)]);
            float4 vv = *reinterpret_cast<const float4*>(&Vs[k * 64 + tx * 4]);
            o[0][0] = fmaf(pv.x, vv.x, o[0][0]); o[0][1] = fmaf(pv.x, vv.y, o[0][1]);
            o[0][2] = fmaf(pv.x, vv.z, o[0][2]); o[0][3] = fmaf(pv.x, vv.w, o[0][3]);
            o[1][0] = fmaf(pv.y, vv.x, o[1][0]); o[1][1] = fmaf(pv.y, vv.y, o[1][1]);
            o[1][2] = fmaf(pv.y, vv.z, o[1][2]); o[1][3] = fmaf(pv.y, vv.w, o[1][3]);
            o[2][0] = fmaf(pv.z, vv.x, o[2][0]); o[2][1] = fmaf(pv.z, vv.y, o[2][1]);
            o[2][2] = fmaf(pv.z, vv.z, o[2][2]); o[2][3] = fmaf(pv.z, vv.w, o[2][3]);
            o[3][0] = fmaf(pv.w, vv.x, o[3][0]); o[3][1] = fmaf(pv.w, vv.y, o[3][1]);
            o[3][2] = fmaf(pv.w, vv.z, o[3][2]); o[3][3] = fmaf(pv.w, vv.w, o[3][3]);
        }
    }

    // epilogue
    #pragma unroll
    for (int i = 0; i < 4; i++) {
        float inv = 1.0f / l[i];
        float4 ov = make_float4(o[i][0] * inv, o[i][1] * inv,
                                o[i][2] * inv, o[i][3] * inv);
        *reinterpret_cast<float4*>(
            &O[(size_t)(q0 + ty * 4 + i) * HIDDEN + head * HD + tx * 4]) = ov;
    }
}

// ---------------- launch ----------------
extern "C" void kernel_launch(void* const* d_in, const int* in_sizes, int n_in,
                              void* d_out, int out_size)
{
    int big[3], bn = 0;
    int med[2], md = 0;
    int posIdx = 5;
    for (int i = 0; i < n_in; i++) {
        if (in_sizes[i] == HIDDEN * HIDDEN)    { if (bn < 3) big[bn++] = i; }
        else if (in_sizes[i] == HIDDEN * KV_W) { if (md < 2) med[md++] = i; }
        else                                   { posIdx = i; }
    }
    int iX, iWq, iWo;
    if (bn == 3 && big[0] == 0) { iX = big[0]; iWq = big[1]; iWo = big[2]; }
    else if (bn == 3)           { iWo = big[0]; iWq = big[1]; iX = big[2]; }
    else                        { iX = 0; iWq = 1; iWo = 4; }
    int iWk = (md == 2) ? med[0] : 2;
    int iWv = (md == 2) ? med[1] : 3;

    const float* X   = (const float*)d_in[iX];
    const float* Wq  = (const float*)d_in[iWq];
    const float* Wk  = (const float*)d_in[iWk];
    const float* Wv  = (const float*)d_in[iWv];
    const float* Wo  = (const float*)d_in[iWo];
    const int*   pos = (const int*)d_in[posIdx];
    float* out = (float*)d_out;

    float *Qp, *Kp, *Vp, *Op;
    cudaGetSymbolAddress((void**)&Qp, g_Q);
    cudaGetSymbolAddress((void**)&Kp, g_K);
    cudaGetSymbolAddress((void**)&Vp, g_V);
    cudaGetSymbolAddress((void**)&Op, g_O);

    // QKV projections
    sgemm128  <<<dim3(HIDDEN / 128, S_LEN / 128), 256>>>(X, Wq, Qp, S_LEN, HIDDEN, HIDDEN);
    sgemm128x64<<<dim3(KV_W / 64,   S_LEN / 128), 256>>>(X, Wk, Kp, S_LEN, KV_W,  HIDDEN);
    sgemm128x64<<<dim3(KV_W / 64,   S_LEN / 128), 256>>>(X, Wv, Vp, S_LEN, KV_W,  HIDDEN);

    // RoPE (negated angle — exact executed-reference semantics)
    {
        int total = S_LEN * (NH + NKV) * 32;
        rope_neg<<<(total + 255) / 256, 256>>>(Qp, Kp, pos);
    }

    // register-tiled causal flash attention
    flash_tile<<<dim3(S_LEN / 64, NH), 256>>>(Qp, Kp, Vp, Op);

    // output projection
    sgemm128<<<dim3(HIDDEN / 128, S_LEN / 128), 256>>>(Op, Wo, out, S_LEN, HIDDEN, HIDDEN);
}